// round 14
// baseline (speedup 1.0000x reference)
#include <cuda_runtime.h>
#include <cuda_bf16.h>
#include <math.h>
#include <stdint.h>

#define BSZ 4096
#define DSZ 512

// ---------------------------------------------------------------------------
// scratch globals (no dynamic allocation anywhere)
// ---------------------------------------------------------------------------
__device__ __align__(16) __nv_bfloat16 g_hi[3][(size_t)BSZ * DSZ];  // 12 MB
__device__ float    g_xt[3][BSZ];
__device__ int      g_lab[BSZ];
__device__ float    g_ent[BSZ];
__device__ float    g_se_row[3][BSZ];
__device__ float    g_se_col[3][BSZ];
__device__ double   g_matched_t[3];
__device__ double   g_acc_entail;
__device__ double   g_acc_contrast;
__device__ unsigned g_done = 0;

// ---------------------------------------------------------------------------
// PTX helpers — baseline ISA only (no sm_103a-gated instructions)
// ---------------------------------------------------------------------------
__device__ __forceinline__ uint32_t smem_u32(const void* p) {
    uint32_t a;
    asm("{ .reg .u64 t; cvta.to.shared.u64 t, %1; cvt.u32.u64 %0, t; }"
        : "=r"(a) : "l"(p));
    return a;
}

__device__ __forceinline__ void cp16(uint32_t s, const void* g) {
    asm volatile("cp.async.cg.shared.global [%0], [%1], 16;"
                 :: "r"(s), "l"(g) : "memory");
}
#define CP_COMMIT() asm volatile("cp.async.commit_group;" ::: "memory")
#define CP_WAIT(n)  asm volatile("cp.async.wait_group %0;" :: "n"(n) : "memory")

__device__ __forceinline__ void ldsm4(uint32_t* r, uint32_t a) {
    asm volatile("ldmatrix.sync.aligned.m8n8.x4.shared.b16 {%0,%1,%2,%3}, [%4];"
                 : "=r"(r[0]), "=r"(r[1]), "=r"(r[2]), "=r"(r[3]) : "r"(a));
}

__device__ __forceinline__ void mma_bf16(float* c, const uint32_t* a,
                                         uint32_t b0, uint32_t b1) {
    asm volatile(
        "mma.sync.aligned.m16n8k16.row.col.f32.bf16.bf16.f32 "
        "{%0,%1,%2,%3}, {%4,%5,%6,%7}, {%8,%9}, {%0,%1,%2,%3};"
        : "+f"(c[0]), "+f"(c[1]), "+f"(c[2]), "+f"(c[3])
        : "r"(a[0]), "r"(a[1]), "r"(a[2]), "r"(a[3]), "r"(b0), "r"(b1));
}

// ---------------------------------------------------------------------------
// prep: grid (BSZ, 5), 128 threads, block-per-row (R12 shape — high MLP).
//  y=0..2 : bf16 convert + time component for set y
//  y=3    : entailment term (dna -> image) -> g_ent[i] (no atomics)
//  y=4    : (bx<32 only) copy labels + zero accumulators (NO smem, NO scan)
// (launch #1)
// ---------------------------------------------------------------------------
__global__ void __launch_bounds__(128)
prep_kernel(const float* __restrict__ img, const float* __restrict__ dna,
            const float* __restrict__ txt, const int* __restrict__ labels,
            const float* __restrict__ pCurv) {
    __shared__ float red[3][128];
    const int set = blockIdx.y;
    const int i   = blockIdx.x;
    const int tid = threadIdx.x;

    if (set < 3) {
        const float* f = (set == 0) ? img : ((set == 1) ? dna : txt);
        const float4 v = ((const float4*)(f + (size_t)i * DSZ))[tid];
        __nv_bfloat162* dh =
            (__nv_bfloat162*)(g_hi[set] + (size_t)i * DSZ) + tid * 2;
        dh[0] = __halves2bfloat162(__float2bfloat16(v.x), __float2bfloat16(v.y));
        dh[1] = __halves2bfloat162(__float2bfloat16(v.z), __float2bfloat16(v.w));
        red[0][tid] = v.x * v.x + v.y * v.y + v.z * v.z + v.w * v.w;
        __syncthreads();
        for (int o = 64; o > 0; o >>= 1) {
            if (tid < o) red[0][tid] += red[0][tid + o];
            __syncthreads();
        }
        if (tid == 0) g_xt[set][i] = sqrtf(1.0f / (*pCurv) + red[0][0]);
    } else if (set == 3) {
        const float4 xv = ((const float4*)(dna + (size_t)i * DSZ))[tid];
        const float4 yv = ((const float4*)(img + (size_t)i * DSZ))[tid];
        red[0][tid] = xv.x * yv.x + xv.y * yv.y + xv.z * yv.z + xv.w * yv.w;
        red[1][tid] = xv.x * xv.x + xv.y * xv.y + xv.z * xv.z + xv.w * xv.w;
        red[2][tid] = yv.x * yv.x + yv.y * yv.y + yv.z * yv.z + yv.w * yv.w;
        __syncthreads();
        for (int o = 64; o > 0; o >>= 1) {
            if (tid < o) {
                red[0][tid] += red[0][tid + o];
                red[1][tid] += red[1][tid + o];
                red[2][tid] += red[2][tid + o];
            }
            __syncthreads();
        }
        if (tid == 0) {
            const float curv  = *pCurv;
            const float dot   = red[0][0];
            const float ndna  = red[1][0];
            const float nimg  = red[2][0];
            const float xt    = sqrtf(1.0f / curv + ndna);   // dna time
            const float yt    = sqrtf(1.0f / curv + nimg);   // image time
            const float normx = sqrtf(ndna);
            const float c     = curv * (dot - xt * yt);
            const float num   = yt + c * xt;
            const float den   = normx * sqrtf(fmaxf(c * c - 1.0f, 0.0f));
            float ain = num / (den + 1e-8f);
            ain = fminf(fmaxf(ain, -1.0f + 1e-8f), 1.0f - 1e-8f);
            const float ang = acosf(ain);
            float asin_in = 0.2f / (normx * sqrtf(curv) + 1e-6f);
            asin_in = fminf(fmaxf(asin_in, -1.0f + 1e-6f), 1.0f - 1e-6f);
            const float ap = asinf(asin_in);
            g_ent[i] = fmaxf(ang - ap, 0.0f);
        }
    } else {
        if (i >= 32) return;
        const int ii = i * 128 + tid;
        g_lab[ii] = labels[ii];
#pragma unroll
        for (int p = 0; p < 3; p++) {
            g_se_row[p][ii] = 0.0f;
            g_se_col[p][ii] = 0.0f;
        }
        if (ii < 3)  g_matched_t[ii] = 0.0;
        if (ii == 0) { g_acc_entail = 0.0; g_acc_contrast = 0.0; g_done = 0; }
    }
}

// ---------------------------------------------------------------------------
// warp-MMA GEMM (single bf16 term, mma.sync m16n8k16) + fused CE epilogue.
// Grid (32,32,3): all 3 pairs in ONE launch. Tile 128x128, BK=64, 3-stage
// cp.async ring, one sync/chunk, 2 CTAs/SM. Row stride 144B.
// cp.async prefetch issued AFTER the first k-step; per-warp rotated k-step
// order desynchronizes LDSM bursts across the SMSP. (launch #2)
// ---------------------------------------------------------------------------
#define STG   36864
#define MOFS  18432
#define CTRL  (3 * STG)                 /* 110592 */
#define GEMM_SMEM (CTRL + 3200)

__device__ __forceinline__ void do_ks(
    float (&acc)[2][8][4], const uint32_t* koA, const uint32_t* koB,
    uint32_t cs, int ks)
{
    uint32_t ah[2][4], bh[4][4];
#pragma unroll
    for (int mi = 0; mi < 2; mi++)
        ldsm4(ah[mi], koA[ks] + cs + mi * 2304);
#pragma unroll
    for (int ng = 0; ng < 4; ng++)
        ldsm4(bh[ng], koB[ks] + cs + ng * 2304);
#pragma unroll
    for (int mi = 0; mi < 2; mi++)
#pragma unroll
        for (int ni = 0; ni < 8; ni++) {
            const int ng = ni >> 1, pe = ni & 1;
            mma_bf16(acc[mi][ni], ah[mi], bh[ng][pe], bh[ng][pe + 2]);
        }
}

__global__ void __launch_bounds__(256, 2)
gemm_ce_wm(const float* __restrict__ pLS, const float* __restrict__ pCurv) {
    extern __shared__ char smem[];
    const int tid  = threadIdx.x;
    const int lane = tid & 31;
    const int wid  = tid >> 5;
    const int warp_m = wid & 3;     // 4 row groups of 32
    const int warp_n = wid >> 2;    // 2 col groups of 64
    const int bx = blockIdx.x, by = blockIdx.y, pair = blockIdx.z;
    const int PA[3] = {0, 0, 1};
    const int PB[3] = {1, 2, 2};
    const int ia = PA[pair], ib = PB[pair];

    const uint32_t sb = smem_u32(smem);

    float* xtA_s  = (float*)(smem + CTRL);
    float* xtB_s  = (float*)(smem + CTRL + 512);
    int*   labA_s = (int*)  (smem + CTRL + 1024);
    int*   labB_s = (int*)  (smem + CTRL + 1536);
    float* erow_s = (float*)(smem + CTRL + 2048);
    float* ecol_s = (float*)(smem + CTRL + 2560);
    float* msum_s = (float*)(smem + CTRL + 3072);

    if (tid < 128) {
        xtA_s[tid]  = g_xt[ia][by * 128 + tid];
        xtB_s[tid]  = g_xt[ib][bx * 128 + tid];
        labA_s[tid] = g_lab[by * 128 + tid];
        labB_s[tid] = g_lab[bx * 128 + tid];
        erow_s[tid] = 0.0f;
        ecol_s[tid] = 0.0f;
    }
    if (tid == 0) *msum_s = 0.0f;

    // --- loop-invariant addresses ---
    const int srow = tid >> 3;
    const int seg  = tid & 7;
    const __nv_bfloat16* pA =
        g_hi[ia] + (size_t)(by * 128 + srow) * DSZ + seg * 8;
    const __nv_bfloat16* pB =
        g_hi[ib] + (size_t)(bx * 128 + srow) * DSZ + seg * 8;
    const uint32_t soA = sb + (uint32_t)(srow * 144 + seg * 16);

    const int rsel = lane & 15;
    const int kh   = (lane >> 4) * 16;
    const uint32_t caA = sb + (uint32_t)((warp_m * 32 + rsel) * 144 + kh);
    const uint32_t caB =
        sb + (uint32_t)(MOFS + (warp_n * 64 + rsel) * 144 + kh);
    // per-warp rotated k-step offsets (desync LDSM bursts across SMSP)
    const int w4 = wid & 3;
    uint32_t koA[4], koB[4];
#pragma unroll
    for (int ks = 0; ks < 4; ks++) {
        const uint32_t ko = (uint32_t)(((ks + w4) & 3) * 32);
        koA[ks] = caA + ko;
        koB[ks] = caB + ko;
    }

    float acc[2][8][4];
#pragma unroll
    for (int mi = 0; mi < 2; mi++)
#pragma unroll
        for (int ni = 0; ni < 8; ni++)
#pragma unroll
            for (int cc = 0; cc < 4; cc++) acc[mi][ni][cc] = 0.0f;

    // prologue: fill stages 0 and 1 (chunks 0, 1)
#pragma unroll
    for (int s = 0; s < 2; s++) {
#pragma unroll
        for (int it = 0; it < 4; it++) {
            cp16(soA + s * STG + it * 4608,        pA + s * 64 + it * 16384);
            cp16(soA + s * STG + MOFS + it * 4608, pB + s * 64 + it * 16384);
        }
        CP_COMMIT();
    }

    // mainloop: 8 chunks, 3-stage ring, single sync per chunk.
#pragma unroll
    for (int k = 0; k < 8; k++) {
        if (k < 7) { CP_WAIT(1); } else { CP_WAIT(0); }
        __syncthreads();
        const uint32_t cs = (k % 3) * STG;
        do_ks(acc, koA, koB, cs, 0);
        if (k < 6) {
            const uint32_t st = ((k + 2) % 3) * STG;
#pragma unroll
            for (int it = 0; it < 4; it++) {
                cp16(soA + st + it * 4608,        pA + (k + 2) * 64 + it * 16384);
                cp16(soA + st + MOFS + it * 4608, pB + (k + 2) * 64 + it * 16384);
            }
            CP_COMMIT();
        }
        do_ks(acc, koA, koB, cs, 1);
        do_ks(acc, koA, koB, cs, 2);
        do_ks(acc, koA, koB, cs, 3);
    }

    // ---- epilogue: logits -> exp sums + matched sum ----
    const float ls    = *pLS;
    const float curv  = *pCurv;
    const float scale = -ls / sqrtf(curv);
    const bool  fastp = (scale == -10.0f);

    float cxa[4];
    int   la[4], rowl[4];
#pragma unroll
    for (int q = 0; q < 4; q++) {                 // q = mi*2 + half
        const int rl = warp_m * 32 + (q >> 1) * 16 + (lane >> 2) + (q & 1) * 8;
        rowl[q] = rl;
        cxa[q]  = curv * xtA_s[rl];
        la[q]   = labA_s[rl];
    }

    float rs[4], cs16[16];
#pragma unroll
    for (int q = 0; q < 4; q++)  rs[q] = 0.0f;
#pragma unroll
    for (int q = 0; q < 16; q++) cs16[q] = 0.0f;
    float msum = 0.0f;

#pragma unroll
    for (int mi = 0; mi < 2; mi++)
#pragma unroll
        for (int ni = 0; ni < 8; ni++)
#pragma unroll
            for (int cc = 0; cc < 4; cc++) {
                const int half = cc >> 1, b = cc & 1;
                const int cl = warp_n * 64 + ni * 8 + (lane & 3) * 2 + b;
                const float dot = acc[mi][ni][cc];
                float cv = fmaf(cxa[mi * 2 + half], xtB_s[cl], -curv * dot);
                cv = fmaxf(cv, 1.0f + 1e-8f);
                float e;
                if (fastp && cv >= 64.0f) {
                    const float x2 = 2.0f * cv;
                    float r = __int_as_float(0x7EF311C3u - __float_as_uint(x2));
                    r = r * fmaf(-x2, r, 2.0f);
                    r = r * fmaf(-x2, r, 2.0f);
                    r = r * fmaf(-x2, r, 2.0f);
                    const float r2 = r * r;
                    const float r4 = r2 * r2;
                    const float r8 = r4 * r4;
                    e = (r8 * r2) * fmaf(10.0f, r2, 1.0f);
                } else {
                    const float u = cv + sqrtf(fmaf(cv, cv, -1.0f));
                    e = exp2f(scale * __log2f(u));
                }
                rs[mi * 2 + half] += e;
                cs16[ni * 2 + b]  += e;
                if (la[mi * 2 + half] == labB_s[cl]) {
                    const float u = cv + sqrtf(fmaf(cv, cv, -1.0f));
                    msum += __log2f(u);
                }
            }

    // row sums: reduce within quad
#pragma unroll
    for (int q = 0; q < 4; q++) {
        float v = rs[q];
        v += __shfl_xor_sync(0xffffffffu, v, 1);
        v += __shfl_xor_sync(0xffffffffu, v, 2);
        if ((lane & 3) == 0) atomicAdd(&erow_s[rowl[q]], v);
    }
    // col sums: reduce across quads
#pragma unroll
    for (int q = 0; q < 16; q++) {                // q = ni*2 + b
        float v = cs16[q];
        v += __shfl_xor_sync(0xffffffffu, v, 4);
        v += __shfl_xor_sync(0xffffffffu, v, 8);
        v += __shfl_xor_sync(0xffffffffu, v, 16);
        if (lane < 4) {
            const int cl = warp_n * 64 + (q >> 1) * 8 + lane * 2 + (q & 1);
            atomicAdd(&ecol_s[cl], v);
        }
    }
    for (int o = 16; o > 0; o >>= 1)
        msum += __shfl_xor_sync(0xffffffffu, msum, o);
    if (lane == 0) atomicAdd(msum_s, msum);
    __syncthreads();

    if (tid < 128) {
        atomicAdd(&g_se_row[pair][by * 128 + tid], erow_s[tid]);
        atomicAdd(&g_se_col[pair][bx * 128 + tid], ecol_s[tid]);
    }
    if (tid == 0) atomicAdd(&g_matched_t[pair], (double)(*msum_s));
}

// ---------------------------------------------------------------------------
// reduce: 32 blocks x 128; computes cnt_i inline from smem label cache,
// then cnt_i*(lse terms) + entail; last block composes output
// (completion-counter pattern; deterministic, graph-capturable). (launch #3)
// ---------------------------------------------------------------------------
__global__ void __launch_bounds__(128)
reduce_kernel(const float* __restrict__ pLS, const float* __restrict__ pCurv,
              float* __restrict__ out, int out_size) {
    __shared__ int    sl[BSZ];
    __shared__ double redc[128];
    __shared__ double rede[128];
    const int tid = threadIdx.x;
    const int i   = blockIdx.x * 128 + tid;
    for (int t = tid; t < BSZ; t += 128) sl[t] = g_lab[t];
    __syncthreads();
    const int li = sl[i];
    int c = 0;
#pragma unroll 8
    for (int j = 0; j < BSZ; j++) c += (sl[j] == li) ? 1 : 0;

    double l = 0.0;
#pragma unroll
    for (int p = 0; p < 3; p++)
        l += (double)logf(g_se_row[p][i]) + (double)logf(g_se_col[p][i]);
    redc[tid] = (double)c * l;
    rede[tid] = (double)g_ent[i];
    __syncthreads();
    for (int o = 64; o > 0; o >>= 1) {
        if (tid < o) { redc[tid] += redc[tid + o]; rede[tid] += rede[tid + o]; }
        __syncthreads();
    }
    if (tid == 0) {
        atomicAdd(&g_acc_contrast, redc[0]);
        atomicAdd(&g_acc_entail,   rede[0]);
        __threadfence();
        const unsigned t = atomicAdd(&g_done, 1u);
        if (t == 31u) {
            g_done = 0;
            const double ls       = (double)(*pLS);
            const double curv     = (double)(*pCurv);
            const double scaleLn2 = -(ls / sqrt(curv)) * 0.6931471805599453;
            double matched = 0.0;
            for (int p = 0; p < 3; p++) matched += g_matched_t[p];
            matched *= scaleLn2;
            const double csum = *(volatile double*)&g_acc_contrast;
            const double esum = *(volatile double*)&g_acc_entail;
            const double contrast = (csum - 2.0 * matched) / (6.0 * (double)BSZ);
            const double entail   = esum / (double)BSZ;
            const double total    = contrast + 0.2 * entail;
            if (out_size > 0) out[0] = (float)total;
            if (out_size > 1) out[1] = (float)contrast;
            if (out_size > 2) out[2] = (float)entail;
        }
    }
}

// ---------------------------------------------------------------------------
extern "C" void kernel_launch(void* const* d_in, const int* in_sizes, int n_in,
                              void* d_out, int out_size) {
    const float* img    = (const float*)d_in[0];
    const float* dna    = (const float*)d_in[1];
    const float* txt    = (const float*)d_in[2];
    const int*   labels = (const int*)d_in[3];   // int32 (JAX x64 disabled)
    const float* pLS    = (const float*)d_in[4];
    const float* pCurv  = (const float*)d_in[5];
    float*       out    = (float*)d_out;

    cudaFuncSetAttribute(gemm_ce_wm,
                         cudaFuncAttributeMaxDynamicSharedMemorySize,
                         GEMM_SMEM);

    prep_kernel<<<dim3(BSZ, 5), 128>>>(img, dna, txt, labels, pCurv);  // #1
    gemm_ce_wm<<<dim3(32, 32, 3), 256, GEMM_SMEM>>>(pLS, pCurv);       // #2
    reduce_kernel<<<32, 128>>>(pLS, pCurv, out, out_size);             // #3
}

// round 15
// speedup vs baseline: 1.5710x; 1.5710x over previous
#include <cuda_runtime.h>
#include <cuda_bf16.h>
#include <math.h>
#include <stdint.h>

#define BSZ 4096
#define DSZ 512

// ---------------------------------------------------------------------------
// scratch globals (no dynamic allocation anywhere)
// ---------------------------------------------------------------------------
__device__ __align__(16) __nv_bfloat16 g_hi[3][(size_t)BSZ * DSZ];  // 12 MB
__device__ float    g_xt[3][BSZ];
__device__ int      g_lab[BSZ];
__device__ float    g_ent[BSZ];
__device__ float    g_se_row[3][BSZ];
__device__ float    g_se_col[3][BSZ];
__device__ double   g_matched_t[3];
__device__ double   g_acc_entail;
__device__ double   g_acc_contrast;
__device__ unsigned g_done = 0;

// ---------------------------------------------------------------------------
// PTX helpers — baseline ISA only (no sm_103a-gated instructions)
// ---------------------------------------------------------------------------
__device__ __forceinline__ uint32_t smem_u32(const void* p) {
    uint32_t a;
    asm("{ .reg .u64 t; cvta.to.shared.u64 t, %1; cvt.u32.u64 %0, t; }"
        : "=r"(a) : "l"(p));
    return a;
}

__device__ __forceinline__ void cp16(uint32_t s, const void* g) {
    asm volatile("cp.async.cg.shared.global [%0], [%1], 16;"
                 :: "r"(s), "l"(g) : "memory");
}
#define CP_COMMIT() asm volatile("cp.async.commit_group;" ::: "memory")
#define CP_WAIT(n)  asm volatile("cp.async.wait_group %0;" :: "n"(n) : "memory")

__device__ __forceinline__ void ldsm4(uint32_t* r, uint32_t a) {
    asm volatile("ldmatrix.sync.aligned.m8n8.x4.shared.b16 {%0,%1,%2,%3}, [%4];"
                 : "=r"(r[0]), "=r"(r[1]), "=r"(r[2]), "=r"(r[3]) : "r"(a));
}

__device__ __forceinline__ void mma_bf16(float* c, const uint32_t* a,
                                         uint32_t b0, uint32_t b1) {
    asm volatile(
        "mma.sync.aligned.m16n8k16.row.col.f32.bf16.bf16.f32 "
        "{%0,%1,%2,%3}, {%4,%5,%6,%7}, {%8,%9}, {%0,%1,%2,%3};"
        : "+f"(c[0]), "+f"(c[1]), "+f"(c[2]), "+f"(c[3])
        : "r"(a[0]), "r"(a[1]), "r"(a[2]), "r"(a[3]), "r"(b0), "r"(b1));
}

// ---------------------------------------------------------------------------
// prep: grid (BSZ, 5), 128 threads, block-per-row (high MLP).
//  y=0..2 : bf16 convert + time component for set y
//  y=3    : entailment term (dna -> image) -> g_ent[i] (no atomics)
//  y=4    : (bx<32 only) copy labels + zero accumulators (NO smem, NO scan)
// (launch #1)
// ---------------------------------------------------------------------------
__global__ void __launch_bounds__(128)
prep_kernel(const float* __restrict__ img, const float* __restrict__ dna,
            const float* __restrict__ txt, const int* __restrict__ labels,
            const float* __restrict__ pCurv) {
    __shared__ float red[3][128];
    const int set = blockIdx.y;
    const int i   = blockIdx.x;
    const int tid = threadIdx.x;

    if (set < 3) {
        const float* f = (set == 0) ? img : ((set == 1) ? dna : txt);
        const float4 v = ((const float4*)(f + (size_t)i * DSZ))[tid];
        __nv_bfloat162* dh =
            (__nv_bfloat162*)(g_hi[set] + (size_t)i * DSZ) + tid * 2;
        dh[0] = __halves2bfloat162(__float2bfloat16(v.x), __float2bfloat16(v.y));
        dh[1] = __halves2bfloat162(__float2bfloat16(v.z), __float2bfloat16(v.w));
        red[0][tid] = v.x * v.x + v.y * v.y + v.z * v.z + v.w * v.w;
        __syncthreads();
        for (int o = 64; o > 0; o >>= 1) {
            if (tid < o) red[0][tid] += red[0][tid + o];
            __syncthreads();
        }
        if (tid == 0) g_xt[set][i] = sqrtf(1.0f / (*pCurv) + red[0][0]);
    } else if (set == 3) {
        const float4 xv = ((const float4*)(dna + (size_t)i * DSZ))[tid];
        const float4 yv = ((const float4*)(img + (size_t)i * DSZ))[tid];
        red[0][tid] = xv.x * yv.x + xv.y * yv.y + xv.z * yv.z + xv.w * yv.w;
        red[1][tid] = xv.x * xv.x + xv.y * xv.y + xv.z * xv.z + xv.w * xv.w;
        red[2][tid] = yv.x * yv.x + yv.y * yv.y + yv.z * yv.z + yv.w * yv.w;
        __syncthreads();
        for (int o = 64; o > 0; o >>= 1) {
            if (tid < o) {
                red[0][tid] += red[0][tid + o];
                red[1][tid] += red[1][tid + o];
                red[2][tid] += red[2][tid + o];
            }
            __syncthreads();
        }
        if (tid == 0) {
            const float curv  = *pCurv;
            const float dot   = red[0][0];
            const float ndna  = red[1][0];
            const float nimg  = red[2][0];
            const float xt    = sqrtf(1.0f / curv + ndna);   // dna time
            const float yt    = sqrtf(1.0f / curv + nimg);   // image time
            const float normx = sqrtf(ndna);
            const float c     = curv * (dot - xt * yt);
            const float num   = yt + c * xt;
            const float den   = normx * sqrtf(fmaxf(c * c - 1.0f, 0.0f));
            float ain = num / (den + 1e-8f);
            ain = fminf(fmaxf(ain, -1.0f + 1e-8f), 1.0f - 1e-8f);
            const float ang = acosf(ain);
            float asin_in = 0.2f / (normx * sqrtf(curv) + 1e-6f);
            asin_in = fminf(fmaxf(asin_in, -1.0f + 1e-6f), 1.0f - 1e-6f);
            const float ap = asinf(asin_in);
            g_ent[i] = fmaxf(ang - ap, 0.0f);
        }
    } else {
        if (i >= 32) return;
        const int ii = i * 128 + tid;
        g_lab[ii] = labels[ii];
#pragma unroll
        for (int p = 0; p < 3; p++) {
            g_se_row[p][ii] = 0.0f;
            g_se_col[p][ii] = 0.0f;
        }
        if (ii < 3)  g_matched_t[ii] = 0.0;
        if (ii == 0) { g_acc_entail = 0.0; g_acc_contrast = 0.0; g_done = 0; }
    }
}

// ---------------------------------------------------------------------------
// warp-MMA GEMM (single bf16 term, mma.sync m16n8k16) + fused CE epilogue.
// Grid (32,32,3): all 3 pairs in ONE launch. Tile 128x128, BK=64, 3-stage
// cp.async ring, one sync/chunk, 2 CTAs/SM. Row stride 144B.
// cp.async prefetch issued AFTER the first k-step; per-warp rotated k-step
// order desynchronizes LDSM bursts across the SMSP. (launch #2)
// ---------------------------------------------------------------------------
#define STG   36864
#define MOFS  18432
#define CTRL  (3 * STG)                 /* 110592 */
#define GEMM_SMEM (CTRL + 3200)

__device__ __forceinline__ void do_ks(
    float (&acc)[2][8][4], const uint32_t* koA, const uint32_t* koB,
    uint32_t cs, int ks)
{
    uint32_t ah[2][4], bh[4][4];
#pragma unroll
    for (int mi = 0; mi < 2; mi++)
        ldsm4(ah[mi], koA[ks] + cs + mi * 2304);
#pragma unroll
    for (int ng = 0; ng < 4; ng++)
        ldsm4(bh[ng], koB[ks] + cs + ng * 2304);
#pragma unroll
    for (int mi = 0; mi < 2; mi++)
#pragma unroll
        for (int ni = 0; ni < 8; ni++) {
            const int ng = ni >> 1, pe = ni & 1;
            mma_bf16(acc[mi][ni], ah[mi], bh[ng][pe], bh[ng][pe + 2]);
        }
}

__global__ void __launch_bounds__(256, 2)
gemm_ce_wm(const float* __restrict__ pLS, const float* __restrict__ pCurv) {
    extern __shared__ char smem[];
    const int tid  = threadIdx.x;
    const int lane = tid & 31;
    const int wid  = tid >> 5;
    const int warp_m = wid & 3;     // 4 row groups of 32
    const int warp_n = wid >> 2;    // 2 col groups of 64
    const int bx = blockIdx.x, by = blockIdx.y, pair = blockIdx.z;
    const int PA[3] = {0, 0, 1};
    const int PB[3] = {1, 2, 2};
    const int ia = PA[pair], ib = PB[pair];

    const uint32_t sb = smem_u32(smem);

    float* xtA_s  = (float*)(smem + CTRL);
    float* xtB_s  = (float*)(smem + CTRL + 512);
    int*   labA_s = (int*)  (smem + CTRL + 1024);
    int*   labB_s = (int*)  (smem + CTRL + 1536);
    float* erow_s = (float*)(smem + CTRL + 2048);
    float* ecol_s = (float*)(smem + CTRL + 2560);
    float* msum_s = (float*)(smem + CTRL + 3072);

    if (tid < 128) {
        xtA_s[tid]  = g_xt[ia][by * 128 + tid];
        xtB_s[tid]  = g_xt[ib][bx * 128 + tid];
        labA_s[tid] = g_lab[by * 128 + tid];
        labB_s[tid] = g_lab[bx * 128 + tid];
        erow_s[tid] = 0.0f;
        ecol_s[tid] = 0.0f;
    }
    if (tid == 0) *msum_s = 0.0f;

    // --- loop-invariant addresses ---
    const int srow = tid >> 3;
    const int seg  = tid & 7;
    const __nv_bfloat16* pA =
        g_hi[ia] + (size_t)(by * 128 + srow) * DSZ + seg * 8;
    const __nv_bfloat16* pB =
        g_hi[ib] + (size_t)(bx * 128 + srow) * DSZ + seg * 8;
    const uint32_t soA = sb + (uint32_t)(srow * 144 + seg * 16);

    const int rsel = lane & 15;
    const int kh   = (lane >> 4) * 16;
    const uint32_t caA = sb + (uint32_t)((warp_m * 32 + rsel) * 144 + kh);
    const uint32_t caB =
        sb + (uint32_t)(MOFS + (warp_n * 64 + rsel) * 144 + kh);
    // per-warp rotated k-step offsets (desync LDSM bursts across SMSP)
    const int w4 = wid & 3;
    uint32_t koA[4], koB[4];
#pragma unroll
    for (int ks = 0; ks < 4; ks++) {
        const uint32_t ko = (uint32_t)(((ks + w4) & 3) * 32);
        koA[ks] = caA + ko;
        koB[ks] = caB + ko;
    }

    float acc[2][8][4];
#pragma unroll
    for (int mi = 0; mi < 2; mi++)
#pragma unroll
        for (int ni = 0; ni < 8; ni++)
#pragma unroll
            for (int cc = 0; cc < 4; cc++) acc[mi][ni][cc] = 0.0f;

    // prologue: fill stages 0 and 1 (chunks 0, 1)
#pragma unroll
    for (int s = 0; s < 2; s++) {
#pragma unroll
        for (int it = 0; it < 4; it++) {
            cp16(soA + s * STG + it * 4608,        pA + s * 64 + it * 16384);
            cp16(soA + s * STG + MOFS + it * 4608, pB + s * 64 + it * 16384);
        }
        CP_COMMIT();
    }

    // mainloop: 8 chunks, 3-stage ring, single sync per chunk.
#pragma unroll
    for (int k = 0; k < 8; k++) {
        if (k < 7) { CP_WAIT(1); } else { CP_WAIT(0); }
        __syncthreads();
        const uint32_t cs = (k % 3) * STG;
        do_ks(acc, koA, koB, cs, 0);
        if (k < 6) {
            const uint32_t st = ((k + 2) % 3) * STG;
#pragma unroll
            for (int it = 0; it < 4; it++) {
                cp16(soA + st + it * 4608,        pA + (k + 2) * 64 + it * 16384);
                cp16(soA + st + MOFS + it * 4608, pB + (k + 2) * 64 + it * 16384);
            }
            CP_COMMIT();
        }
        do_ks(acc, koA, koB, cs, 1);
        do_ks(acc, koA, koB, cs, 2);
        do_ks(acc, koA, koB, cs, 3);
    }

    // ---- epilogue: logits -> exp sums + matched sum ----
    const float ls    = *pLS;
    const float curv  = *pCurv;
    const float scale = -ls / sqrtf(curv);
    const bool  fastp = (scale == -10.0f);

    float cxa[4];
    int   la[4], rowl[4];
#pragma unroll
    for (int q = 0; q < 4; q++) {                 // q = mi*2 + half
        const int rl = warp_m * 32 + (q >> 1) * 16 + (lane >> 2) + (q & 1) * 8;
        rowl[q] = rl;
        cxa[q]  = curv * xtA_s[rl];
        la[q]   = labA_s[rl];
    }

    float rs[4], cs16[16];
#pragma unroll
    for (int q = 0; q < 4; q++)  rs[q] = 0.0f;
#pragma unroll
    for (int q = 0; q < 16; q++) cs16[q] = 0.0f;
    float msum = 0.0f;

#pragma unroll
    for (int mi = 0; mi < 2; mi++)
#pragma unroll
        for (int ni = 0; ni < 8; ni++)
#pragma unroll
            for (int cc = 0; cc < 4; cc++) {
                const int half = cc >> 1, b = cc & 1;
                const int cl = warp_n * 64 + ni * 8 + (lane & 3) * 2 + b;
                const float dot = acc[mi][ni][cc];
                float cv = fmaf(cxa[mi * 2 + half], xtB_s[cl], -curv * dot);
                cv = fmaxf(cv, 1.0f + 1e-8f);
                float e;
                if (fastp && cv >= 64.0f) {
                    const float x2 = 2.0f * cv;
                    float r = __int_as_float(0x7EF311C3u - __float_as_uint(x2));
                    r = r * fmaf(-x2, r, 2.0f);
                    r = r * fmaf(-x2, r, 2.0f);
                    r = r * fmaf(-x2, r, 2.0f);
                    const float r2 = r * r;
                    const float r4 = r2 * r2;
                    const float r8 = r4 * r4;
                    e = (r8 * r2) * fmaf(10.0f, r2, 1.0f);
                } else {
                    const float u = cv + sqrtf(fmaf(cv, cv, -1.0f));
                    e = exp2f(scale * __log2f(u));
                }
                rs[mi * 2 + half] += e;
                cs16[ni * 2 + b]  += e;
                if (la[mi * 2 + half] == labB_s[cl]) {
                    const float u = cv + sqrtf(fmaf(cv, cv, -1.0f));
                    msum += __log2f(u);
                }
            }

    // row sums: reduce within quad
#pragma unroll
    for (int q = 0; q < 4; q++) {
        float v = rs[q];
        v += __shfl_xor_sync(0xffffffffu, v, 1);
        v += __shfl_xor_sync(0xffffffffu, v, 2);
        if ((lane & 3) == 0) atomicAdd(&erow_s[rowl[q]], v);
    }
    // col sums: reduce across quads
#pragma unroll
    for (int q = 0; q < 16; q++) {                // q = ni*2 + b
        float v = cs16[q];
        v += __shfl_xor_sync(0xffffffffu, v, 4);
        v += __shfl_xor_sync(0xffffffffu, v, 8);
        v += __shfl_xor_sync(0xffffffffu, v, 16);
        if (lane < 4) {
            const int cl = warp_n * 64 + (q >> 1) * 8 + lane * 2 + (q & 1);
            atomicAdd(&ecol_s[cl], v);
        }
    }
    for (int o = 16; o > 0; o >>= 1)
        msum += __shfl_xor_sync(0xffffffffu, msum, o);
    if (lane == 0) atomicAdd(msum_s, msum);
    __syncthreads();

    if (tid < 128) {
        atomicAdd(&g_se_row[pair][by * 128 + tid], erow_s[tid]);
        atomicAdd(&g_se_col[pair][bx * 128 + tid], ecol_s[tid]);
    }
    if (tid == 0) atomicAdd(&g_matched_t[pair], (double)(*msum_s));
}

// ---------------------------------------------------------------------------
// reduce: 32 blocks x 128; computes cnt_i inline from smem label cache
// (int4 vectorized scan), then cnt_i*(lse terms) + entail; last block
// composes output (completion-counter; deterministic). (launch #3)
// ---------------------------------------------------------------------------
__global__ void __launch_bounds__(128)
reduce_kernel(const float* __restrict__ pLS, const float* __restrict__ pCurv,
              float* __restrict__ out, int out_size) {
    __shared__ __align__(16) int sl[BSZ];
    __shared__ double redc[128];
    __shared__ double rede[128];
    const int tid = threadIdx.x;
    const int i   = blockIdx.x * 128 + tid;
    for (int t = tid; t < BSZ; t += 128) sl[t] = g_lab[t];
    __syncthreads();
    const int li = sl[i];
    int c = 0;
    const int4* sl4 = (const int4*)sl;
#pragma unroll 4
    for (int j = 0; j < BSZ / 4; j++) {
        const int4 v = sl4[j];
        c += (v.x == li) + (v.y == li) + (v.z == li) + (v.w == li);
    }

    double l = 0.0;
#pragma unroll
    for (int p = 0; p < 3; p++)
        l += (double)logf(g_se_row[p][i]) + (double)logf(g_se_col[p][i]);
    redc[tid] = (double)c * l;
    rede[tid] = (double)g_ent[i];
    __syncthreads();
    for (int o = 64; o > 0; o >>= 1) {
        if (tid < o) { redc[tid] += redc[tid + o]; rede[tid] += rede[tid + o]; }
        __syncthreads();
    }
    if (tid == 0) {
        atomicAdd(&g_acc_contrast, redc[0]);
        atomicAdd(&g_acc_entail,   rede[0]);
        __threadfence();
        const unsigned t = atomicAdd(&g_done, 1u);
        if (t == 31u) {
            g_done = 0;
            const double ls       = (double)(*pLS);
            const double curv     = (double)(*pCurv);
            const double scaleLn2 = -(ls / sqrt(curv)) * 0.6931471805599453;
            double matched = 0.0;
            for (int p = 0; p < 3; p++) matched += g_matched_t[p];
            matched *= scaleLn2;
            const double csum = *(volatile double*)&g_acc_contrast;
            const double esum = *(volatile double*)&g_acc_entail;
            const double contrast = (csum - 2.0 * matched) / (6.0 * (double)BSZ);
            const double entail   = esum / (double)BSZ;
            const double total    = contrast + 0.2 * entail;
            if (out_size > 0) out[0] = (float)total;
            if (out_size > 1) out[1] = (float)contrast;
            if (out_size > 2) out[2] = (float)entail;
        }
    }
}

// ---------------------------------------------------------------------------
extern "C" void kernel_launch(void* const* d_in, const int* in_sizes, int n_in,
                              void* d_out, int out_size) {
    const float* img    = (const float*)d_in[0];
    const float* dna    = (const float*)d_in[1];
    const float* txt    = (const float*)d_in[2];
    const int*   labels = (const int*)d_in[3];   // int32 (JAX x64 disabled)
    const float* pLS    = (const float*)d_in[4];
    const float* pCurv  = (const float*)d_in[5];
    float*       out    = (float*)d_out;

    cudaFuncSetAttribute(gemm_ce_wm,
                         cudaFuncAttributeMaxDynamicSharedMemorySize,
                         GEMM_SMEM);

    prep_kernel<<<dim3(BSZ, 5), 128>>>(img, dna, txt, labels, pCurv);  // #1
    gemm_ce_wm<<<dim3(32, 32, 3), 256, GEMM_SMEM>>>(pLS, pCurv);       // #2
    reduce_kernel<<<32, 128>>>(pLS, pCurv, out, out_size);             // #3
}

// round 16
// speedup vs baseline: 1.7154x; 1.0919x over previous
#include <cuda_runtime.h>
#include <cuda_bf16.h>
#include <math.h>
#include <stdint.h>

#define BSZ 4096
#define DSZ 512

// ---------------------------------------------------------------------------
// scratch globals (no dynamic allocation anywhere)
// ---------------------------------------------------------------------------
__device__ __align__(16) __nv_bfloat16 g_hi[3][(size_t)BSZ * DSZ];  // 12 MB
__device__ float    g_xt[3][BSZ];
__device__ int      g_lab[BSZ];
__device__ float    g_ent[BSZ];
__device__ float    g_se_row[3][BSZ];
__device__ float    g_se_col[3][BSZ];
__device__ double   g_matched_t[3];
__device__ double   g_acc_entail;
__device__ double   g_acc_contrast;
__device__ unsigned g_done = 0;

// ---------------------------------------------------------------------------
// PTX helpers — baseline ISA only (no sm_103a-gated instructions)
// ---------------------------------------------------------------------------
__device__ __forceinline__ uint32_t smem_u32(const void* p) {
    uint32_t a;
    asm("{ .reg .u64 t; cvta.to.shared.u64 t, %1; cvt.u32.u64 %0, t; }"
        : "=r"(a) : "l"(p));
    return a;
}

__device__ __forceinline__ void cp16(uint32_t s, const void* g) {
    asm volatile("cp.async.cg.shared.global [%0], [%1], 16;"
                 :: "r"(s), "l"(g) : "memory");
}
#define CP_COMMIT() asm volatile("cp.async.commit_group;" ::: "memory")
#define CP_WAIT(n)  asm volatile("cp.async.wait_group %0;" :: "n"(n) : "memory")

__device__ __forceinline__ void ldsm4(uint32_t* r, uint32_t a) {
    asm volatile("ldmatrix.sync.aligned.m8n8.x4.shared.b16 {%0,%1,%2,%3}, [%4];"
                 : "=r"(r[0]), "=r"(r[1]), "=r"(r[2]), "=r"(r[3]) : "r"(a));
}

__device__ __forceinline__ void mma_bf16(float* c, const uint32_t* a,
                                         uint32_t b0, uint32_t b1) {
    asm volatile(
        "mma.sync.aligned.m16n8k16.row.col.f32.bf16.bf16.f32 "
        "{%0,%1,%2,%3}, {%4,%5,%6,%7}, {%8,%9}, {%0,%1,%2,%3};"
        : "+f"(c[0]), "+f"(c[1]), "+f"(c[2]), "+f"(c[3])
        : "r"(a[0]), "r"(a[1]), "r"(a[2]), "r"(a[3]), "r"(b0), "r"(b1));
}

// ---------------------------------------------------------------------------
// prep: grid (BSZ, 4), 128 threads, block-per-row (high MLP).
//  y=0   : bf16 convert + time component for image
//  y=1   : bf16 convert + time component for dna + ENTAILMENT (reads img too)
//  y=2   : bf16 convert + time component for text
//  y=3   : (bx<32 only) copy labels + zero accumulators
// (launch #1)
// ---------------------------------------------------------------------------
__global__ void __launch_bounds__(128)
prep_kernel(const float* __restrict__ img, const float* __restrict__ dna,
            const float* __restrict__ txt, const int* __restrict__ labels,
            const float* __restrict__ pCurv) {
    __shared__ float red[3][128];
    const int set = blockIdx.y;
    const int i   = blockIdx.x;
    const int tid = threadIdx.x;

    if (set == 0 || set == 2) {
        const float* f = (set == 0) ? img : txt;
        const float4 v = ((const float4*)(f + (size_t)i * DSZ))[tid];
        __nv_bfloat162* dh =
            (__nv_bfloat162*)(g_hi[set] + (size_t)i * DSZ) + tid * 2;
        dh[0] = __halves2bfloat162(__float2bfloat16(v.x), __float2bfloat16(v.y));
        dh[1] = __halves2bfloat162(__float2bfloat16(v.z), __float2bfloat16(v.w));
        red[0][tid] = v.x * v.x + v.y * v.y + v.z * v.z + v.w * v.w;
        __syncthreads();
        for (int o = 64; o > 0; o >>= 1) {
            if (tid < o) red[0][tid] += red[0][tid + o];
            __syncthreads();
        }
        if (tid == 0) g_xt[set][i] = sqrtf(1.0f / (*pCurv) + red[0][0]);
    } else if (set == 1) {
        // dna: convert + xt + entailment (vs image)
        const float4 xv = ((const float4*)(dna + (size_t)i * DSZ))[tid];
        const float4 yv = ((const float4*)(img + (size_t)i * DSZ))[tid];
        __nv_bfloat162* dh =
            (__nv_bfloat162*)(g_hi[1] + (size_t)i * DSZ) + tid * 2;
        dh[0] = __halves2bfloat162(__float2bfloat16(xv.x), __float2bfloat16(xv.y));
        dh[1] = __halves2bfloat162(__float2bfloat16(xv.z), __float2bfloat16(xv.w));
        red[0][tid] = xv.x * xv.x + xv.y * xv.y + xv.z * xv.z + xv.w * xv.w;
        red[1][tid] = xv.x * yv.x + xv.y * yv.y + xv.z * yv.z + xv.w * yv.w;
        red[2][tid] = yv.x * yv.x + yv.y * yv.y + yv.z * yv.z + yv.w * yv.w;
        __syncthreads();
        for (int o = 64; o > 0; o >>= 1) {
            if (tid < o) {
                red[0][tid] += red[0][tid + o];
                red[1][tid] += red[1][tid + o];
                red[2][tid] += red[2][tid + o];
            }
            __syncthreads();
        }
        if (tid == 0) {
            const float curv  = *pCurv;
            const float ndna  = red[0][0];
            const float dot   = red[1][0];
            const float nimg  = red[2][0];
            const float xt    = sqrtf(1.0f / curv + ndna);   // dna time
            const float yt    = sqrtf(1.0f / curv + nimg);   // image time
            g_xt[1][i] = xt;
            const float normx = sqrtf(ndna);
            const float c     = curv * (dot - xt * yt);
            const float num   = yt + c * xt;
            const float den   = normx * sqrtf(fmaxf(c * c - 1.0f, 0.0f));
            float ain = num / (den + 1e-8f);
            ain = fminf(fmaxf(ain, -1.0f + 1e-8f), 1.0f - 1e-8f);
            const float ang = acosf(ain);
            float asin_in = 0.2f / (normx * sqrtf(curv) + 1e-6f);
            asin_in = fminf(fmaxf(asin_in, -1.0f + 1e-6f), 1.0f - 1e-6f);
            const float ap = asinf(asin_in);
            g_ent[i] = fmaxf(ang - ap, 0.0f);
        }
    } else {
        if (i >= 32) return;
        const int ii = i * 128 + tid;
        g_lab[ii] = labels[ii];
#pragma unroll
        for (int p = 0; p < 3; p++) {
            g_se_row[p][ii] = 0.0f;
            g_se_col[p][ii] = 0.0f;
        }
        if (ii < 3)  g_matched_t[ii] = 0.0;
        if (ii == 0) { g_acc_entail = 0.0; g_acc_contrast = 0.0; g_done = 0; }
    }
}

// ---------------------------------------------------------------------------
// warp-MMA GEMM (single bf16 term, mma.sync m16n8k16) + fused CE epilogue.
// Grid (32,32,3): all 3 pairs in ONE launch. Tile 128x128, BK=64, 3-stage
// cp.async ring, one sync/chunk, 2 CTAs/SM. Row stride 144B.
// Epilogue pipe-balance: even columns use the Newton-FMA fast path (FMA
// pipe), odd columns use sqrt+log2+exp2 (MUFU pipe, exact; t reused for the
// matched-label sum). (launch #2)
// ---------------------------------------------------------------------------
#define STG   36864
#define MOFS  18432
#define CTRL  (3 * STG)                 /* 110592 */
#define GEMM_SMEM (CTRL + 3200)

__device__ __forceinline__ void do_ks(
    float (&acc)[2][8][4], const uint32_t* koA, const uint32_t* koB,
    uint32_t cs, int ks)
{
    uint32_t ah[2][4], bh[4][4];
#pragma unroll
    for (int mi = 0; mi < 2; mi++)
        ldsm4(ah[mi], koA[ks] + cs + mi * 2304);
#pragma unroll
    for (int ng = 0; ng < 4; ng++)
        ldsm4(bh[ng], koB[ks] + cs + ng * 2304);
#pragma unroll
    for (int mi = 0; mi < 2; mi++)
#pragma unroll
        for (int ni = 0; ni < 8; ni++) {
            const int ng = ni >> 1, pe = ni & 1;
            mma_bf16(acc[mi][ni], ah[mi], bh[ng][pe], bh[ng][pe + 2]);
        }
}

__global__ void __launch_bounds__(256, 2)
gemm_ce_wm(const float* __restrict__ pLS, const float* __restrict__ pCurv) {
    extern __shared__ char smem[];
    const int tid  = threadIdx.x;
    const int lane = tid & 31;
    const int wid  = tid >> 5;
    const int warp_m = wid & 3;     // 4 row groups of 32
    const int warp_n = wid >> 2;    // 2 col groups of 64
    const int bx = blockIdx.x, by = blockIdx.y, pair = blockIdx.z;
    const int PA[3] = {0, 0, 1};
    const int PB[3] = {1, 2, 2};
    const int ia = PA[pair], ib = PB[pair];

    const uint32_t sb = smem_u32(smem);

    float* xtA_s  = (float*)(smem + CTRL);
    float* xtB_s  = (float*)(smem + CTRL + 512);
    int*   labA_s = (int*)  (smem + CTRL + 1024);
    int*   labB_s = (int*)  (smem + CTRL + 1536);
    float* erow_s = (float*)(smem + CTRL + 2048);
    float* ecol_s = (float*)(smem + CTRL + 2560);
    float* msum_s = (float*)(smem + CTRL + 3072);

    if (tid < 128) {
        xtA_s[tid]  = g_xt[ia][by * 128 + tid];
        xtB_s[tid]  = g_xt[ib][bx * 128 + tid];
        labA_s[tid] = g_lab[by * 128 + tid];
        labB_s[tid] = g_lab[bx * 128 + tid];
        erow_s[tid] = 0.0f;
        ecol_s[tid] = 0.0f;
    }
    if (tid == 0) *msum_s = 0.0f;

    // --- loop-invariant addresses ---
    const int srow = tid >> 3;
    const int seg  = tid & 7;
    const __nv_bfloat16* pA =
        g_hi[ia] + (size_t)(by * 128 + srow) * DSZ + seg * 8;
    const __nv_bfloat16* pB =
        g_hi[ib] + (size_t)(bx * 128 + srow) * DSZ + seg * 8;
    const uint32_t soA = sb + (uint32_t)(srow * 144 + seg * 16);

    const int rsel = lane & 15;
    const int kh   = (lane >> 4) * 16;
    const uint32_t caA = sb + (uint32_t)((warp_m * 32 + rsel) * 144 + kh);
    const uint32_t caB =
        sb + (uint32_t)(MOFS + (warp_n * 64 + rsel) * 144 + kh);
    // per-warp rotated k-step offsets (desync LDSM bursts across SMSP)
    const int w4 = wid & 3;
    uint32_t koA[4], koB[4];
#pragma unroll
    for (int ks = 0; ks < 4; ks++) {
        const uint32_t ko = (uint32_t)(((ks + w4) & 3) * 32);
        koA[ks] = caA + ko;
        koB[ks] = caB + ko;
    }

    float acc[2][8][4];
#pragma unroll
    for (int mi = 0; mi < 2; mi++)
#pragma unroll
        for (int ni = 0; ni < 8; ni++)
#pragma unroll
            for (int cc = 0; cc < 4; cc++) acc[mi][ni][cc] = 0.0f;

    // prologue: fill stages 0 and 1 (chunks 0, 1)
#pragma unroll
    for (int s = 0; s < 2; s++) {
#pragma unroll
        for (int it = 0; it < 4; it++) {
            cp16(soA + s * STG + it * 4608,        pA + s * 64 + it * 16384);
            cp16(soA + s * STG + MOFS + it * 4608, pB + s * 64 + it * 16384);
        }
        CP_COMMIT();
    }

    // mainloop: 8 chunks, 3-stage ring, single sync per chunk.
#pragma unroll
    for (int k = 0; k < 8; k++) {
        if (k < 7) { CP_WAIT(1); } else { CP_WAIT(0); }
        __syncthreads();
        const uint32_t cs = (k % 3) * STG;
        do_ks(acc, koA, koB, cs, 0);
        if (k < 6) {
            const uint32_t st = ((k + 2) % 3) * STG;
#pragma unroll
            for (int it = 0; it < 4; it++) {
                cp16(soA + st + it * 4608,        pA + (k + 2) * 64 + it * 16384);
                cp16(soA + st + MOFS + it * 4608, pB + (k + 2) * 64 + it * 16384);
            }
            CP_COMMIT();
        }
        do_ks(acc, koA, koB, cs, 1);
        do_ks(acc, koA, koB, cs, 2);
        do_ks(acc, koA, koB, cs, 3);
    }

    // ---- epilogue: logits -> exp sums + matched sum ----
    const float ls    = *pLS;
    const float curv  = *pCurv;
    const float scale = -ls / sqrtf(curv);
    const bool  fastp = (scale == -10.0f);

    float cxa[4];
    int   la[4], rowl[4];
#pragma unroll
    for (int q = 0; q < 4; q++) {                 // q = mi*2 + half
        const int rl = warp_m * 32 + (q >> 1) * 16 + (lane >> 2) + (q & 1) * 8;
        rowl[q] = rl;
        cxa[q]  = curv * xtA_s[rl];
        la[q]   = labA_s[rl];
    }

    float rs[4], cs16[16];
#pragma unroll
    for (int q = 0; q < 4; q++)  rs[q] = 0.0f;
#pragma unroll
    for (int q = 0; q < 16; q++) cs16[q] = 0.0f;
    float msum = 0.0f;

#pragma unroll
    for (int mi = 0; mi < 2; mi++)
#pragma unroll
        for (int ni = 0; ni < 8; ni++)
#pragma unroll
            for (int cc = 0; cc < 4; cc++) {
                const int half = cc >> 1, b = cc & 1;
                const int cl = warp_n * 64 + ni * 8 + (lane & 3) * 2 + b;
                const float dot = acc[mi][ni][cc];
                float cv = fmaf(cxa[mi * 2 + half], xtB_s[cl], -curv * dot);
                cv = fmaxf(cv, 1.0f + 1e-8f);
                const bool match = (la[mi * 2 + half] == labB_s[cl]);
                float e;
                if (b == 1) {
                    // MUFU pipe path (exact); reuse t for matched sum
                    const float u = cv + sqrtf(fmaf(cv, cv, -1.0f));
                    const float t = __log2f(u);
                    e = exp2f(scale * t);
                    if (match) msum += t;
                } else {
                    if (fastp && cv >= 64.0f) {
                        const float x2 = 2.0f * cv;
                        float r = __int_as_float(0x7EF311C3u - __float_as_uint(x2));
                        r = r * fmaf(-x2, r, 2.0f);
                        r = r * fmaf(-x2, r, 2.0f);
                        r = r * fmaf(-x2, r, 2.0f);
                        const float r2 = r * r;
                        const float r4 = r2 * r2;
                        const float r8 = r4 * r4;
                        e = (r8 * r2) * fmaf(10.0f, r2, 1.0f);
                    } else {
                        const float u = cv + sqrtf(fmaf(cv, cv, -1.0f));
                        e = exp2f(scale * __log2f(u));
                    }
                    if (match) {
                        const float u = cv + sqrtf(fmaf(cv, cv, -1.0f));
                        msum += __log2f(u);
                    }
                }
                rs[mi * 2 + half] += e;
                cs16[ni * 2 + b]  += e;
            }

    // row sums: reduce within quad
#pragma unroll
    for (int q = 0; q < 4; q++) {
        float v = rs[q];
        v += __shfl_xor_sync(0xffffffffu, v, 1);
        v += __shfl_xor_sync(0xffffffffu, v, 2);
        if ((lane & 3) == 0) atomicAdd(&erow_s[rowl[q]], v);
    }
    // col sums: reduce across quads
#pragma unroll
    for (int q = 0; q < 16; q++) {                // q = ni*2 + b
        float v = cs16[q];
        v += __shfl_xor_sync(0xffffffffu, v, 4);
        v += __shfl_xor_sync(0xffffffffu, v, 8);
        v += __shfl_xor_sync(0xffffffffu, v, 16);
        if (lane < 4) {
            const int cl = warp_n * 64 + (q >> 1) * 8 + lane * 2 + (q & 1);
            atomicAdd(&ecol_s[cl], v);
        }
    }
    for (int o = 16; o > 0; o >>= 1)
        msum += __shfl_xor_sync(0xffffffffu, msum, o);
    if (lane == 0) atomicAdd(msum_s, msum);
    __syncthreads();

    if (tid < 128) {
        atomicAdd(&g_se_row[pair][by * 128 + tid], erow_s[tid]);
        atomicAdd(&g_se_col[pair][bx * 128 + tid], ecol_s[tid]);
    }
    if (tid == 0) atomicAdd(&g_matched_t[pair], (double)(*msum_s));
}

// ---------------------------------------------------------------------------
// reduce: 32 blocks x 128; computes cnt_i inline from smem label cache
// (int4 vectorized scan), then cnt_i*(lse terms) + entail; last block
// composes output (completion-counter; deterministic). (launch #3)
// ---------------------------------------------------------------------------
__global__ void __launch_bounds__(128)
reduce_kernel(const float* __restrict__ pLS, const float* __restrict__ pCurv,
              float* __restrict__ out, int out_size) {
    __shared__ __align__(16) int sl[BSZ];
    __shared__ double redc[128];
    __shared__ double rede[128];
    const int tid = threadIdx.x;
    const int i   = blockIdx.x * 128 + tid;
    for (int t = tid; t < BSZ; t += 128) sl[t] = g_lab[t];
    __syncthreads();
    const int li = sl[i];
    int c = 0;
    const int4* sl4 = (const int4*)sl;
#pragma unroll 4
    for (int j = 0; j < BSZ / 4; j++) {
        const int4 v = sl4[j];
        c += (v.x == li) + (v.y == li) + (v.z == li) + (v.w == li);
    }

    double l = 0.0;
#pragma unroll
    for (int p = 0; p < 3; p++)
        l += (double)logf(g_se_row[p][i]) + (double)logf(g_se_col[p][i]);
    redc[tid] = (double)c * l;
    rede[tid] = (double)g_ent[i];
    __syncthreads();
    for (int o = 64; o > 0; o >>= 1) {
        if (tid < o) { redc[tid] += redc[tid + o]; rede[tid] += rede[tid + o]; }
        __syncthreads();
    }
    if (tid == 0) {
        atomicAdd(&g_acc_contrast, redc[0]);
        atomicAdd(&g_acc_entail,   rede[0]);
        __threadfence();
        const unsigned t = atomicAdd(&g_done, 1u);
        if (t == 31u) {
            g_done = 0;
            const double ls       = (double)(*pLS);
            const double curv     = (double)(*pCurv);
            const double scaleLn2 = -(ls / sqrt(curv)) * 0.6931471805599453;
            double matched = 0.0;
            for (int p = 0; p < 3; p++) matched += g_matched_t[p];
            matched *= scaleLn2;
            const double csum = *(volatile double*)&g_acc_contrast;
            const double esum = *(volatile double*)&g_acc_entail;
            const double contrast = (csum - 2.0 * matched) / (6.0 * (double)BSZ);
            const double entail   = esum / (double)BSZ;
            const double total    = contrast + 0.2 * entail;
            if (out_size > 0) out[0] = (float)total;
            if (out_size > 1) out[1] = (float)contrast;
            if (out_size > 2) out[2] = (float)entail;
        }
    }
}

// ---------------------------------------------------------------------------
extern "C" void kernel_launch(void* const* d_in, const int* in_sizes, int n_in,
                              void* d_out, int out_size) {
    const float* img    = (const float*)d_in[0];
    const float* dna    = (const float*)d_in[1];
    const float* txt    = (const float*)d_in[2];
    const int*   labels = (const int*)d_in[3];   // int32 (JAX x64 disabled)
    const float* pLS    = (const float*)d_in[4];
    const float* pCurv  = (const float*)d_in[5];
    float*       out    = (float*)d_out;

    cudaFuncSetAttribute(gemm_ce_wm,
                         cudaFuncAttributeMaxDynamicSharedMemorySize,
                         GEMM_SMEM);

    prep_kernel<<<dim3(BSZ, 4), 128>>>(img, dna, txt, labels, pCurv);  // #1
    gemm_ce_wm<<<dim3(32, 32, 3), 256, GEMM_SMEM>>>(pLS, pCurv);       // #2
    reduce_kernel<<<32, 128>>>(pLS, pCurv, out, out_size);             // #3
}